// round 4
// baseline (speedup 1.0000x reference)
#include <cuda_runtime.h>
#include <cstdint>

// Packed f32x2 FMA — only reachable via PTX (ptxas never auto-fuses 2x fmaf).
#define FMA2(d, a, b, c) \
    asm("fma.rn.f32x2 %0, %1, %2, %3;" : "=l"(d) : "l"(a), "l"(b), "l"(c))

__device__ __forceinline__ unsigned long long pack2(float lo, float hi) {
    unsigned long long r;
    asm("mov.b64 %0, {%1, %2};" : "=l"(r) : "f"(lo), "f"(hi));
    return r;
}

namespace {
constexpr int H  = 224;
constexpr int W  = 224;
constexpr int HO = 222;
constexpr int WO = 222;
constexpr int OC = 64;
constexpr int TPB = 224;   // 2 row-pairs x 2 channel-quarters x 56 x-slots
}

// Block covers: 4 output rows x 222 cols x 32 channels x 1 batch.
// Thread: 2 rows x 4 cols x 16 channels  -> 8 outputs share each weight fetch.
// Grid (56 y-tiles, 2 ch-groups, 32 batches) = 3584 blocks = 803k threads.
__global__ __launch_bounds__(TPB, 3)
void Conv2d_68298569941797_kernel(const float* __restrict__ data,
                                  const float* __restrict__ weight,
                                  float* __restrict__ out) {
    __shared__ float s_in[6 * W];                 // input rows y0..y0+5 (row-clamped)
    __shared__ unsigned long long s_w[OC * 10];   // 9 packed (w,w) + pad per channel

    const int tid = threadIdx.x;
    const int b   = blockIdx.z;
    const int y0  = blockIdx.x * 4;               // output-row base (even)

    // Stage 6 input rows (clamped: y0=220 tile touches rows up to 225 -> clamp 223).
    for (int i = tid; i < 6 * W; i += TPB) {
        int rr = i / W;
        int cc = i - rr * W;
        int gr = y0 + rr;
        if (gr > H - 1) gr = H - 1;
        s_in[i] = data[((size_t)b * H + gr) * W + cc];
    }
    // Stage all weights packed (w,w); only our 32-channel half is read.
    for (int i = tid; i < OC * 9; i += TPB) {
        int o = i / 9;
        int k = i - o * 9;
        float w = weight[i];
        s_w[o * 10 + k] = pack2(w, w);
    }
    __syncthreads();

    const int rp  = tid / 112;            // row pair: 0 -> rows y0,y0+1; 1 -> y0+2,y0+3
    const int rem = tid - rp * 112;
    const int chq = rem / 56;             // channel quarter within this block
    const int q   = rem - chq * 56;       // x slot 0..55
    const int x0  = (q < 55) ? 4 * q : 220;
    const bool quad = (q < 55);           // q=55 -> only pair (220,221)

    // Input window: 4 rows (2rp .. 2rp+3) x 5 sliding pairs over cols x0..x0+5.
    const int c4 = (x0 + 4 < W) ? x0 + 4 : W - 1;   // clamp only matters for q=55
    const int c5 = (x0 + 5 < W) ? x0 + 5 : W - 1;
    unsigned long long P[4][5];
#pragma unroll
    for (int rr = 0; rr < 4; ++rr) {
        const float* rp_ = s_in + (2 * rp + rr) * W;
        float a0 = rp_[x0], a1 = rp_[x0 + 1], a2 = rp_[x0 + 2], a3 = rp_[x0 + 3];
        float a4 = rp_[c4], a5 = rp_[c5];
        P[rr][0] = pack2(a0, a1);
        P[rr][1] = pack2(a1, a2);
        P[rr][2] = pack2(a2, a3);
        P[rr][3] = pack2(a3, a4);
        P[rr][4] = pack2(a4, a5);
    }

    const int gr0 = y0 + 2 * rp;          // even global output row
    const int gr1 = gr0 + 1;
    const bool v0 = (gr0 < HO);
    const bool v1 = (gr1 < HO);
    if (!v0 && !v1) return;               // tail tile, rows 222/223

    const int cbase = (blockIdx.y * 2 + chq) * 16;
    const size_t plane = (size_t)HO * WO;
    float* op = out + (((size_t)b * OC + cbase) * HO + gr0) * WO + x0;
    const ulonglong2* w2 = reinterpret_cast<const ulonglong2*>(s_w) + (size_t)cbase * 5;

#pragma unroll 2
    for (int o = 0; o < 16; ++o) {
        const ulonglong2* wo = w2 + o * 5;
        ulonglong2 w01 = wo[0];
        ulonglong2 w23 = wo[1];
        ulonglong2 w45 = wo[2];
        ulonglong2 w67 = wo[3];
        ulonglong2 w8x = wo[4];   // .y is padding

        unsigned long long A00 = 0ull, A01 = 0ull, A10 = 0ull, A11 = 0ull;

        // Row gr0, pair (x0, x0+1)
        FMA2(A00, P[0][0], w01.x, A00); FMA2(A00, P[0][1], w01.y, A00); FMA2(A00, P[0][2], w23.x, A00);
        FMA2(A00, P[1][0], w23.y, A00); FMA2(A00, P[1][1], w45.x, A00); FMA2(A00, P[1][2], w45.y, A00);
        FMA2(A00, P[2][0], w67.x, A00); FMA2(A00, P[2][1], w67.y, A00); FMA2(A00, P[2][2], w8x.x, A00);
        // Row gr0, pair (x0+2, x0+3)
        FMA2(A01, P[0][2], w01.x, A01); FMA2(A01, P[0][3], w01.y, A01); FMA2(A01, P[0][4], w23.x, A01);
        FMA2(A01, P[1][2], w23.y, A01); FMA2(A01, P[1][3], w45.x, A01); FMA2(A01, P[1][4], w45.y, A01);
        FMA2(A01, P[2][2], w67.x, A01); FMA2(A01, P[2][3], w67.y, A01); FMA2(A01, P[2][4], w8x.x, A01);
        // Row gr1, pair (x0, x0+1)
        FMA2(A10, P[1][0], w01.x, A10); FMA2(A10, P[1][1], w01.y, A10); FMA2(A10, P[1][2], w23.x, A10);
        FMA2(A10, P[2][0], w23.y, A10); FMA2(A10, P[2][1], w45.x, A10); FMA2(A10, P[2][2], w45.y, A10);
        FMA2(A10, P[3][0], w67.x, A10); FMA2(A10, P[3][1], w67.y, A10); FMA2(A10, P[3][2], w8x.x, A10);
        // Row gr1, pair (x0+2, x0+3)
        FMA2(A11, P[1][2], w01.x, A11); FMA2(A11, P[1][3], w01.y, A11); FMA2(A11, P[1][4], w23.x, A11);
        FMA2(A11, P[2][2], w23.y, A11); FMA2(A11, P[2][3], w45.x, A11); FMA2(A11, P[2][4], w45.y, A11);
        FMA2(A11, P[3][2], w67.x, A11); FMA2(A11, P[3][3], w67.y, A11); FMA2(A11, P[3][4], w8x.x, A11);

        if (v0) {
            if (quad) {
                // Even row: 16B-aligned (gr0*888 % 16 == 0, 4*x0 % 16 == 0) -> STG.128
                ulonglong2 v; v.x = A00; v.y = A01;
                *reinterpret_cast<ulonglong2*>(op) = v;
            } else {
                *reinterpret_cast<unsigned long long*>(op) = A00;
            }
        }
        if (v1) {
            // Odd row: base offset 8 mod 16 -> two STG.64
            *reinterpret_cast<unsigned long long*>(op + WO) = A10;
            if (quad) *reinterpret_cast<unsigned long long*>(op + WO + 2) = A11;
        }
        op += plane;
    }
}

extern "C" void kernel_launch(void* const* d_in, const int* in_sizes, int n_in,
                              void* d_out, int out_size) {
    const float* data   = (const float*)d_in[0];
    const float* weight = (const float*)d_in[1];
    float* out          = (float*)d_out;

    dim3 grid((HO + 3) / 4, 2, 32);   // (56, 2, 32)
    Conv2d_68298569941797_kernel<<<grid, TPB>>>(data, weight, out);
}